// round 17
// baseline (speedup 1.0000x reference)
#include <cuda_runtime.h>
#include <cuda_bf16.h>
#include <stdint.h>
#include <math.h>

#define Bn 32
#define Hn 1024
#define Sn 1024

// ---------------- scratch (device globals; no allocation allowed) ----------
__device__ float g_A1[Bn * Hn];
__device__ float g_logits[Bn * Sn];
__device__ __nv_bfloat16 g_W2bf[Hn * Hn];         // [h][k]  K-major
__device__ __nv_bfloat16 g_encT[Bn * Sn * Hn];    // [b][s][k] = enc[b][k][s]

// ---------------- helpers ---------------------------------------------------
__device__ __forceinline__ uint32_t smem_u32(const void* p) {
    uint32_t a;
    asm("{ .reg .u64 t; cvta.to.shared.u64 t, %1; cvt.u32.u64 %0, t; }" : "=r"(a) : "l"(p));
    return a;
}
__device__ __forceinline__ float fast_tanh(float x) {
    float y;
    asm("tanh.approx.f32 %0, %1;" : "=f"(y) : "f"(x));
    return y;
}
__device__ __forceinline__ uint32_t pack_bf2(float a, float b) {
    __nv_bfloat162 t = __floats2bfloat162_rn(a, b);
    return *reinterpret_cast<uint32_t*>(&t);
}
#define CP_ASYNC16(smem_a, gptr) \
    asm volatile("cp.async.cg.shared.global [%0], [%1], 16;" :: "r"(smem_a), "l"(gptr) : "memory")

#define LDSM_X4(r, addr) \
    asm volatile("ldmatrix.sync.aligned.m8n8.x4.shared.b16 {%0,%1,%2,%3}, [%4];" \
        : "=r"((r)[0]), "=r"((r)[1]), "=r"((r)[2]), "=r"((r)[3]) : "r"(addr))

#define MMA16816(d, a, b0, b1) \
    asm volatile("mma.sync.aligned.m16n8k16.row.col.f32.bf16.bf16.f32 " \
        "{%0,%1,%2,%3}, {%4,%5,%6,%7}, {%8,%9}, {%0,%1,%2,%3};" \
        : "+f"((d)[0]), "+f"((d)[1]), "+f"((d)[2]), "+f"((d)[3]) \
        : "r"((a)[0]), "r"((a)[1]), "r"((a)[2]), "r"((a)[3]), "r"(b0), "r"(b1))

// SMEM layout for k_energy: 3-stage pipeline, K-chunk = 64
#define STAGE_BYTES 36864
#define A_OFF(s) (1024 + (s) * STAGE_BYTES)
#define B_OFF(s) (1024 + (s) * STAGE_BYTES + 18432)
#define SMEM_BYTES (1024 + 3 * STAGE_BYTES)   // 111616
#define LDB 144                                // row stride bytes (72 bf16)

// ---------------------------------------------------------------------------
// k_prep (merged): block ranges do independent prep work concurrently.
//   [0, 8192)      encT[b][s][k] = bf16(enc[b][k][s])  (64x64 tiles)
//   [8192, 9216)   W2 -> bf16 K-major; first 128 also zero g_logits
//   [9216, 10240)  A1[b,h] for one h, all 32 b (W1 row cached in smem)
//   [10240, 10272) zero ctx output region
// ---------------------------------------------------------------------------
__global__ __launch_bounds__(256) void k_prep(const float* __restrict__ enc,
                                              const float* __restrict__ W,
                                              const float* __restrict__ hidden,
                                              const float* __restrict__ bias,
                                              float* __restrict__ ctx_out) {
    __shared__ float sh[64 * 67];                // 17152 B
    const int bid = blockIdx.x, tid = threadIdx.x;

    if (bid < 8192) {
        // ---- encT transpose-convert ----
        int b = bid >> 8, k0 = ((bid >> 4) & 15) * 64, s0 = (bid & 15) * 64;
        const float* src = enc + ((size_t)b * Sn + k0) * Hn + s0;
#pragma unroll
        for (int it = 0; it < 4; it++) {
            int i = tid + it * 256;              // 1024 float4 slots
            int r = i >> 4, c = i & 15;
            float4 f = *(const float4*)(src + (size_t)r * Hn + c * 4);
            float* tp = &sh[r * 67 + c * 4];
            tp[0] = f.x; tp[1] = f.y; tp[2] = f.z; tp[3] = f.w;
        }
        __syncthreads();
        // Conflict-free gather: warp = 32 consecutive srow at fixed kg
        // bank(j) = (3*(8kg+j) + srow) mod 32, srow spans 0..31 -> 32 banks.
        __nv_bfloat16* dst = g_encT + ((size_t)b * Sn + s0) * Hn + k0;
        {
            int srow = tid & 63, kgq = tid >> 6;     // kgq 0..3
#pragma unroll
            for (int t = 0; t < 2; t++) {
                int kg = kgq * 2 + t;                // 0..7
                const float* col = &sh[kg * 8 * 67 + srow];
                uint4 o;
                o.x = pack_bf2(col[0 * 67], col[1 * 67]);
                o.y = pack_bf2(col[2 * 67], col[3 * 67]);
                o.z = pack_bf2(col[4 * 67], col[5 * 67]);
                o.w = pack_bf2(col[6 * 67], col[7 * 67]);
                *(uint4*)(dst + (size_t)srow * Hn + kg * 8) = o;
            }
        }
    } else if (bid < 9216) {
        // ---- W2 convert ----
        int row = bid - 8192;
        const float4* src = (const float4*)(W + (size_t)row * (2 * Hn) + Hn);
        float4 f = src[tid];
        __nv_bfloat162* dst = (__nv_bfloat162*)(g_W2bf + (size_t)row * Hn);
        dst[2 * tid]     = __floats2bfloat162_rn(f.x, f.y);
        dst[2 * tid + 1] = __floats2bfloat162_rn(f.z, f.w);
        if (row < 128) g_logits[row * 256 + tid] = 0.f;
    } else if (bid < 10240) {
        // ---- A1 for h = bid - 9216, all 32 b ----
        int h = bid - 9216;
        const float* wr = W + (size_t)h * (2 * Hn);
#pragma unroll
        for (int t = 0; t < 4; t++) sh[tid + t * 256] = wr[tid + t * 256];
        __syncthreads();
        int w = tid >> 5, lane = tid & 31;
        float bv = bias[h];
#pragma unroll
        for (int i = 0; i < 4; i++) {
            int b = w + i * 8;
            const float* hr = hidden + (size_t)b * Hn;
            float s = 0.f;
#pragma unroll 4
            for (int j = lane; j < Hn; j += 32) s += sh[j] * hr[j];
#pragma unroll
            for (int o = 16; o; o >>= 1) s += __shfl_xor_sync(0xffffffffu, s, o);
            if (lane == 0) g_A1[b * Hn + h] = s + bv;
        }
    } else {
        // ---- zero ctx region of output ----
        int b = bid - 10240;
        float4 z = make_float4(0.f, 0.f, 0.f, 0.f);
        ((float4*)(ctx_out + (size_t)b * Hn))[tid] = z;
    }
}

// ---------------------------------------------------------------------------
// chunk loader: A[128 x 64] from W2bf, B[128 x 64] from encT (bf16, cp.async)
// ---------------------------------------------------------------------------
__device__ __forceinline__ void load_chunk(int tid,
                                           const __nv_bfloat16* gW,
                                           const __nv_bfloat16* gE,
                                           int kc, uint32_t aBase, uint32_t bBase) {
#pragma unroll
    for (int t = 0; t < 4; t++) {
        int idx = tid + t * 256;
        int r = idx >> 3, c = idx & 7;
        CP_ASYNC16(aBase + r * LDB + c * 16, gW + (size_t)r * Hn + kc + c * 8);
    }
#pragma unroll
    for (int t = 0; t < 4; t++) {
        int idx = tid + t * 256;
        int r = idx >> 3, c = idx & 7;
        CP_ASYNC16(bBase + r * LDB + c * 16, gE + (size_t)r * Hn + kc + c * 8);
    }
    asm volatile("cp.async.commit_group;" ::: "memory");
}

// ---------------------------------------------------------------------------
// k_energy: one CTA per (b, h-tile=128, s-tile=128).   (UNCHANGED — plateau)
// D[h,s] = sum_k W2bf[h,k] * encT[b,s,k]  via mma.sync m16n8k16 bf16 (HMMA).
// 3-stage cp.async pipeline, K-chunk = 64, one barrier per chunk.
// Epilogue: logits[b,s] += sum_h v[h] * tanh(A1[b,h] + D[h,s])
// ---------------------------------------------------------------------------
__global__ __launch_bounds__(256, 2) void k_energy(const float* __restrict__ v) {
    extern __shared__ char smem[];
    uint32_t sb = smem_u32(smem);
    float* sLog = (float*)smem;

    const int tid = threadIdx.x;
    const int l   = tid & 31;
    const int w   = tid >> 5;
    const int wr  = w >> 1;     // 0..3 : h-subtile (32 rows)
    const int wc  = w & 1;      // 0..1 : s-subtile (64 cols)
    const int b   = blockIdx.z;
    const int hc  = blockIdx.y * 128;
    const int sc  = blockIdx.x * 128;

    if (tid < 128) sLog[tid] = 0.f;

    const __nv_bfloat16* gW = g_W2bf + (size_t)hc * Hn;
    const __nv_bfloat16* gE = g_encT + ((size_t)b * Sn + sc) * Hn;

    float acc[2][8][4];
#pragma unroll
    for (int mi = 0; mi < 2; mi++)
#pragma unroll
        for (int ni = 0; ni < 8; ni++)
#pragma unroll
            for (int j = 0; j < 4; j++) acc[mi][ni][j] = 0.f;

    const int a_row  = l & 15;
    const int a_kh   = (l >> 4) * 8;
    const int b_nr   = (l & 7) | ((l >> 4) << 3);
    const int b_kh   = ((l >> 3) & 1) * 8;

    load_chunk(tid, gW, gE, 0 * 64, sb + A_OFF(0), sb + B_OFF(0));
    load_chunk(tid, gW, gE, 1 * 64, sb + A_OFF(1), sb + B_OFF(1));

    for (int i = 0; i < 16; i++) {
        const int cur = i % 3;
        if (i < 15) {
            asm volatile("cp.async.wait_group 1;" ::: "memory");
        } else {
            asm volatile("cp.async.wait_group 0;" ::: "memory");
        }
        __syncthreads();
        if (i + 2 < 16) {
            load_chunk(tid, gW, gE, (i + 2) * 64,
                       sb + A_OFF((i + 2) % 3), sb + B_OFF((i + 2) % 3));
        }
        uint32_t aT = sb + A_OFF(cur);
        uint32_t bT = sb + B_OFF(cur);
#pragma unroll
        for (int k16 = 0; k16 < 4; k16++) {
            uint32_t ar[2][4], br[4][4];
            int kb = (k16 * 16) * 2;
#pragma unroll
            for (int mi = 0; mi < 2; mi++)
                LDSM_X4(ar[mi], aT + (uint32_t)((wr * 32 + mi * 16 + a_row) * LDB) + kb + a_kh * 2);
#pragma unroll
            for (int g = 0; g < 4; g++)
                LDSM_X4(br[g], bT + (uint32_t)((wc * 64 + g * 16 + b_nr) * LDB) + kb + b_kh * 2);
#pragma unroll
            for (int mi = 0; mi < 2; mi++)
#pragma unroll
                for (int ni = 0; ni < 8; ni++)
                    MMA16816(acc[mi][ni], ar[mi], br[ni >> 1][(ni & 1) * 2],
                             br[ni >> 1][(ni & 1) * 2 + 1]);
        }
    }

    // ---- epilogue ----
    float a1v[2][2], vv[2][2];
#pragma unroll
    for (int mi = 0; mi < 2; mi++)
#pragma unroll
        for (int j = 0; j < 2; j++) {
            int h = hc + wr * 32 + mi * 16 + (l >> 2) + j * 8;
            a1v[mi][j] = g_A1[b * Hn + h];
            vv[mi][j]  = v[h];
        }

    float part[8][2];
#pragma unroll
    for (int ni = 0; ni < 8; ni++) { part[ni][0] = 0.f; part[ni][1] = 0.f; }
#pragma unroll
    for (int mi = 0; mi < 2; mi++)
#pragma unroll
        for (int ni = 0; ni < 8; ni++) {
            part[ni][0] += vv[mi][0] * fast_tanh(a1v[mi][0] + acc[mi][ni][0]);
            part[ni][1] += vv[mi][0] * fast_tanh(a1v[mi][0] + acc[mi][ni][1]);
            part[ni][0] += vv[mi][1] * fast_tanh(a1v[mi][1] + acc[mi][ni][2]);
            part[ni][1] += vv[mi][1] * fast_tanh(a1v[mi][1] + acc[mi][ni][3]);
        }
#pragma unroll
    for (int ni = 0; ni < 8; ni++)
#pragma unroll
        for (int e = 0; e < 2; e++) {
            float s = part[ni][e];
            s += __shfl_xor_sync(0xffffffffu, s, 4);
            s += __shfl_xor_sync(0xffffffffu, s, 8);
            s += __shfl_xor_sync(0xffffffffu, s, 16);
            if (l < 4) atomicAdd(&sLog[wc * 64 + ni * 8 + (l & 3) * 2 + e], s);
        }
    __syncthreads();
    if (tid < 128) atomicAdd(&g_logits[b * Sn + sc + tid], sLog[tid]);
}

// ---------------------------------------------------------------------------
// k_ctx_fused: per block (b, s-chunk of 64): recompute softmax from logits,
// then context partial over its s range (float4 h-loads, all 1024 h).
// (y==0) blocks write scores out.                       (UNCHANGED — at cap)
// ---------------------------------------------------------------------------
__global__ __launch_bounds__(256) void k_ctx_fused(const float* __restrict__ enc,
                                                   float* __restrict__ out_ctx,
                                                   float* __restrict__ scores_out,
                                                   int write_out) {
    __shared__ float ssc[Sn];
    __shared__ float red[8];
    const int b  = blockIdx.x;
    const int s0 = blockIdx.y * 64;
    const int tid = threadIdx.x;
    const int lane = tid & 31, wid = tid >> 5;

    float lv[4];
    float m = -1e30f;
#pragma unroll
    for (int t = 0; t < 4; t++) {
        lv[t] = g_logits[b * Sn + tid + t * 256];
        m = fmaxf(m, lv[t]);
    }
#pragma unroll
    for (int o = 16; o; o >>= 1) m = fmaxf(m, __shfl_xor_sync(0xffffffffu, m, o));
    if (lane == 0) red[wid] = m;
    __syncthreads();
    if (wid == 0) {
        float x = red[lane & 7];
#pragma unroll
        for (int o = 4; o; o >>= 1) x = fmaxf(x, __shfl_xor_sync(0xffffffffu, x, o));
        if (lane == 0) red[0] = x;
    }
    __syncthreads();
    m = red[0];
    float s = 0.f;
#pragma unroll
    for (int t = 0; t < 4; t++) {
        lv[t] = __expf(lv[t] - m);
        s += lv[t];
    }
#pragma unroll
    for (int o = 16; o; o >>= 1) s += __shfl_xor_sync(0xffffffffu, s, o);
    __syncthreads();
    if (lane == 0) red[wid] = s;
    __syncthreads();
    if (wid == 0) {
        float x = red[lane & 7];
#pragma unroll
        for (int o = 4; o; o >>= 1) x += __shfl_xor_sync(0xffffffffu, x, o);
        if (lane == 0) red[0] = x;
    }
    __syncthreads();
    float inv = 1.f / red[0];
#pragma unroll
    for (int t = 0; t < 4; t++) {
        float sv = lv[t] * inv;
        ssc[tid + t * 256] = sv;
        if (write_out && blockIdx.y == 0) scores_out[b * Sn + tid + t * 256] = sv;
    }
    __syncthreads();

    const float4* e = (const float4*)(enc + ((size_t)b * Sn + s0) * Hn) + tid;
    float4 acc = make_float4(0.f, 0.f, 0.f, 0.f);
#pragma unroll 8
    for (int si = 0; si < 64; si++) {
        float wsc = ssc[s0 + si];
        float4 f = e[(size_t)si * 256];
        acc.x += wsc * f.x;
        acc.y += wsc * f.y;
        acc.z += wsc * f.z;
        acc.w += wsc * f.w;
    }
    float* dst = out_ctx + (size_t)b * Hn + tid * 4;
    atomicAdd(dst + 0, acc.x);
    atomicAdd(dst + 1, acc.y);
    atomicAdd(dst + 2, acc.z);
    atomicAdd(dst + 3, acc.w);
}

// ---------------------------------------------------------------------------
extern "C" void kernel_launch(void* const* d_in, const int* in_sizes, int n_in,
                              void* d_out, int out_size) {
    const float* hidden = (const float*)d_in[0];
    const float* enc    = (const float*)d_in[1];
    const float* W      = (const float*)d_in[2];
    const float* bias   = (const float*)d_in[3];
    const float* v      = (const float*)d_in[4];

    float* out = (float*)d_out;
    float* ctx = out;                 // context: [B, H]
    float* scr = out + Bn * Hn;       // scores:  [B, 1, S]
    int write_scores = (out_size >= Bn * Hn + Bn * Sn) ? 1 : 0;

    cudaFuncSetAttribute(k_energy, cudaFuncAttributeMaxDynamicSharedMemorySize, SMEM_BYTES);

    k_prep<<<10272, 256>>>(enc, W, hidden, bias, ctx);

    k_energy<<<dim3(8, 8, 32), 256, SMEM_BYTES>>>(v);

    k_ctx_fused<<<dim3(32, 16), 256>>>(enc, ctx, scr, write_scores);
}